// round 17
// baseline (speedup 1.0000x reference)
#include <cuda_runtime.h>
#include <cuda_fp16.h>
#include <mma.h>
#include <math.h>

using namespace nvcuda;

#define N_NODES 40000
#define PAD_N   40064            // 313 * 128
#define N_EDGES 640000
#define DIM     128
#define QKV_LD  384              // [q:128 | kv interleaved:256]
#define HID     512
#define LN_EPS  1e-5f

// ---------------- scratch (device globals; no allocation allowed) ----------
static __device__ __half g_qkv [(size_t)PAD_N * QKV_LD]; // [q | kv-interleaved]
static __device__ float  g_rst [(size_t)PAD_N * DIM];    // post-LN1 (float)
static __device__ __half g_w1_h[128 * 512];              // W1 half [k][n]
static __device__ __half g_w2_h[512 * 128];              // W2 half [k][n]
static __device__ int    g_off[N_NODES + 1];             // CSR offsets (by dst)
static __device__ int    g_cur[N_NODES];                 // counts / cursors (zeroed by cleanup)
static __device__ int    g_esrc[N_EDGES];                // src ids sorted by dst
static __device__ unsigned long long g_state[256];       // lookback scan state (zeroed by cleanup)

// ---------------- cp.async helpers -----------------------------------------
__device__ __forceinline__ void cp16(void* smem, const void* gmem)
{
    unsigned s = (unsigned)__cvta_generic_to_shared(smem);
    asm volatile("cp.async.ca.shared.global [%0], [%1], 16;\n" :: "r"(s), "l"(gmem));
}
#define CP_COMMIT() asm volatile("cp.async.commit_group;\n" ::)
#define CP_WAIT(n)  asm volatile("cp.async.wait_group %0;\n" :: "n"(n))

// ---------------- mma.sync helpers ------------------------------------------
__device__ __forceinline__ unsigned smaddr(const void* p)
{
    return (unsigned)__cvta_generic_to_shared(p);
}
__device__ __forceinline__ void ldsm_x4(unsigned a, unsigned& r0, unsigned& r1,
                                        unsigned& r2, unsigned& r3)
{
    asm volatile("ldmatrix.sync.aligned.m8n8.x4.shared.b16 {%0,%1,%2,%3}, [%4];"
                 : "=r"(r0), "=r"(r1), "=r"(r2), "=r"(r3) : "r"(a));
}
__device__ __forceinline__ void ldsm_x4t(unsigned a, unsigned& r0, unsigned& r1,
                                         unsigned& r2, unsigned& r3)
{
    asm volatile("ldmatrix.sync.aligned.m8n8.x4.trans.shared.b16 {%0,%1,%2,%3}, [%4];"
                 : "=r"(r0), "=r"(r1), "=r"(r2), "=r"(r3) : "r"(a));
}
__device__ __forceinline__ void mma16816(float* c,
                                         unsigned a0, unsigned a1, unsigned a2, unsigned a3,
                                         unsigned b0, unsigned b1)
{
    asm volatile("mma.sync.aligned.m16n8k16.row.col.f32.f16.f16.f32 "
                 "{%0,%1,%2,%3}, {%4,%5,%6,%7}, {%8,%9}, {%0,%1,%2,%3};"
                 : "+f"(c[0]), "+f"(c[1]), "+f"(c[2]), "+f"(c[3])
                 : "r"(a0), "r"(a1), "r"(a2), "r"(a3), "r"(b0), "r"(b1));
}

// ---------------- QKV GEMM, self-contained fp32->fp16 -----------------------
#define QSM_BYTES 69632

__global__ __launch_bounds__(256, 2)
void mm_qkv_kernel(const float* __restrict__ feat,
                   const float* __restrict__ Wq,
                   const float* __restrict__ Wk,
                   const float* __restrict__ Wv,
                   __half* __restrict__ C)
{
    extern __shared__ __align__(16) char smc[];
    __half* As = (__half*)smc;                 // 128x136
    __half* Bs = As + 128 * 136;               // 128x136
    float (*Cs)[132] = (float(*)[132]) smc;    // epilogue reuse

    const int tid = threadIdx.x;
    const int wid = tid >> 5;
    const int rowBase = blockIdx.x * 128;
    const int z = blockIdx.z;
    const float* W = (z == 0) ? Wq : (z == 1) ? Wk : Wv;

    const int wm = wid >> 1;
    const int wn = wid & 1;

#pragma unroll
    for (int it = 0; it < 16; it++) {
        const int idx = tid + it * 256;
        const int r = idx >> 5, c4 = (idx & 31) * 4;
        const int grow = rowBase + r;
        float4 v = (grow < N_NODES)
                 ? *(const float4*)(feat + (size_t)grow * DIM + c4)
                 : make_float4(0, 0, 0, 0);
        *(__half2*)(As + r * 136 + c4)     = __floats2half2_rn(v.x, v.y);
        *(__half2*)(As + r * 136 + c4 + 2) = __floats2half2_rn(v.z, v.w);
        float4 w = *(const float4*)(W + (size_t)r * DIM + c4);
        *(__half2*)(Bs + r * 136 + c4)     = __floats2half2_rn(w.x, w.y);
        *(__half2*)(Bs + r * 136 + c4 + 2) = __floats2half2_rn(w.z, w.w);
    }
    __syncthreads();

    wmma::fragment<wmma::accumulator, 16, 16, 16, float> acc[2][4];
#pragma unroll
    for (int i = 0; i < 2; i++)
#pragma unroll
        for (int j = 0; j < 4; j++) wmma::fill_fragment(acc[i][j], 0.f);

#pragma unroll
    for (int kk = 0; kk < 128; kk += 16) {
        wmma::fragment<wmma::matrix_a, 16, 16, 16, __half, wmma::row_major> fa[2];
        wmma::fragment<wmma::matrix_b, 16, 16, 16, __half, wmma::row_major> fb[4];
#pragma unroll
        for (int i = 0; i < 2; i++)
            wmma::load_matrix_sync(fa[i], As + (wm * 32 + i * 16) * 136 + kk, 136);
#pragma unroll
        for (int j = 0; j < 4; j++)
            wmma::load_matrix_sync(fb[j], Bs + kk * 136 + wn * 64 + j * 16, 136);
#pragma unroll
        for (int i = 0; i < 2; i++)
#pragma unroll
            for (int j = 0; j < 4; j++)
                wmma::mma_sync(acc[i][j], fa[i], fb[j], acc[i][j]);
    }
    __syncthreads();

#pragma unroll
    for (int i = 0; i < 2; i++)
#pragma unroll
        for (int j = 0; j < 4; j++)
            wmma::store_matrix_sync(&Cs[wm * 32 + i * 16][wn * 64 + j * 16],
                                    acc[i][j], 132, wmma::mem_row_major);
    __syncthreads();

#pragma unroll
    for (int it = 0; it < 16; it++) {
        const int lin = tid + it * 256;
        const int r = lin >> 5, c4 = (lin & 31) * 4;
        float4 v = *(const float4*)&Cs[r][c4];
        __half2 h0 = __floats2half2_rn(v.x, v.y);
        __half2 h1 = __floats2half2_rn(v.z, v.w);
        __half* rowp = C + (size_t)(rowBase + r) * QKV_LD;
        __half* dstp = (z == 0) ? (rowp + c4)
                                : (rowp + 128 + 2 * c4 + (z == 2 ? 4 : 0));
        *(__half2*)(dstp)     = h0;
        *(__half2*)(dstp + 2) = h1;
    }
}

// ---------------- fused FFN: PReLU(rst@W1+b1)@W2 + b2 + rst -> LN2 -> out ---
#define FBM 64
#define FSM_A   0                       // 64x136 half
#define FSM_W0  17408                   // W1 chunk 128x136 half
#define FSM_W1  52224                   // W2 chunk 128x136 half
#define FSM_H   87040                   // h chunk 64x136 half
#define FSM_TOTAL 104448                // 2 blocks/SM

__global__ __launch_bounds__(256, 2)
void ffn_fused_kernel(const float* __restrict__ b1,
                      const float* __restrict__ pw,
                      const float* __restrict__ b2,
                      const float* __restrict__ lng,
                      const float* __restrict__ lnb,
                      float* __restrict__ out)
{
    extern __shared__ __align__(16) char sm[];
    __half* As  = (__half*)(sm + FSM_A);
    __half* W1t = (__half*)(sm + FSM_W0);
    __half* W2t = (__half*)(sm + FSM_W1);
    __half* Hs  = (__half*)(sm + FSM_H);
    float (*Cs)[132] = (float(*)[132]) sm;     // epilogue reuse

    const int tid = threadIdx.x;
    const int wid = tid >> 5;
    const int lane = tid & 31;
    const int rowBase = blockIdx.x * FBM;

    const int wr = (wid >> 1) * 16;
    const int wc = (wid & 1) * 64;
    const int lrow = lane & 15;
    const int lcol8 = (lane >> 4) << 3;

    // stage A from float rst (inline convert) + W1 chunk 0 via cp.async
    {
        const float* srcA = g_rst + (size_t)rowBase * DIM;
#pragma unroll
        for (int it = 0; it < 8; it++) {
            int idx = tid + it * 256;             // float4 idx over 64x32
            int r = idx >> 5, c4 = (idx & 31) * 4;
            float4 v = *(const float4*)(srcA + (size_t)r * DIM + c4);
            *(__half2*)(As + r * 136 + c4)     = __floats2half2_rn(v.x, v.y);
            *(__half2*)(As + r * 136 + c4 + 2) = __floats2half2_rn(v.z, v.w);
        }
#pragma unroll
        for (int it = 0; it < 8; it++) {
            int idx = tid + it * 256;
            int r = idx >> 4, c8 = (idx & 15) * 8;
            cp16(W1t + r * 136 + c8, g_w1_h + r * HID + c8);
        }
        CP_COMMIT();
    }
    __syncthreads();            // A visible

    // hoist A fragments (identical for all 4 hidden chunks)
    unsigned afr[8][4];
#pragma unroll
    for (int k = 0; k < 8; k++)
        ldsm_x4(smaddr(As + (wr + lrow) * 136 + k * 16 + lcol8),
                afr[k][0], afr[k][1], afr[k][2], afr[k][3]);

    float y[32];
#pragma unroll
    for (int i = 0; i < 32; i++) y[i] = 0.f;

    for (int c = 0; c < 4; c++) {
        CP_WAIT(0);            // W1_c ready
        __syncthreads();

        // prefetch W2_c during GEMM1
#pragma unroll
        for (int it = 0; it < 8; it++) {
            int idx = tid + it * 256;
            int r = idx >> 4, c8 = (idx & 15) * 8;
            cp16(W2t + r * 136 + c8, g_w2_h + (size_t)(c * 128 + r) * DIM + c8);
        }
        CP_COMMIT();

        // GEMM1: h = A @ W1_c  (A fragments from registers)
        float h[32];
#pragma unroll
        for (int i = 0; i < 32; i++) h[i] = 0.f;
#pragma unroll
        for (int k = 0; k < 8; k++) {
            unsigned b[16];
#pragma unroll
            for (int j = 0; j < 4; j++)
                ldsm_x4t(smaddr(W1t + (k * 16 + lrow) * 136 + wc + 16 * j + lcol8),
                         b[4*j], b[4*j+1], b[4*j+2], b[4*j+3]);
#pragma unroll
            for (int n = 0; n < 8; n++)
                mma16816(&h[n*4], afr[k][0], afr[k][1], afr[k][2], afr[k][3],
                         b[4*(n>>1) + (n&1)*2], b[4*(n>>1) + (n&1)*2 + 1]);
        }

        // bias + PReLU, convert to half, store h chunk to smem
#pragma unroll
        for (int n = 0; n < 8; n++) {
            const int colb = wc + n * 8 + (lane & 3) * 2;
            const int gc = c * 128 + colb;
            const float bi0 = __ldg(b1 + gc), bi1 = __ldg(b1 + gc + 1);
            const float p0 = __ldg(pw + gc),  p1 = __ldg(pw + gc + 1);
            float v0 = h[n*4+0] + bi0;
            float v1 = h[n*4+1] + bi1;
            float v2 = h[n*4+2] + bi0;
            float v3 = h[n*4+3] + bi1;
            v0 = v0 >= 0.f ? v0 : v0 * p0;
            v1 = v1 >= 0.f ? v1 : v1 * p1;
            v2 = v2 >= 0.f ? v2 : v2 * p0;
            v3 = v3 >= 0.f ? v3 : v3 * p1;
            const int r0 = wr + (lane >> 2);
            *(__half2*)(Hs + r0 * 136 + colb)       = __floats2half2_rn(v0, v1);
            *(__half2*)(Hs + (r0 + 8) * 136 + colb) = __floats2half2_rn(v2, v3);
        }
        __syncthreads();       // h visible; W1t free

        if (c < 3) {
#pragma unroll
            for (int it = 0; it < 8; it++) {
                int idx = tid + it * 256;
                int r = idx >> 4, c8 = (idx & 15) * 8;
                cp16(W1t + r * 136 + c8, g_w1_h + r * HID + (c + 1) * 128 + c8);
            }
            CP_COMMIT();
            CP_WAIT(1);        // W2_c ready
        } else {
            CP_WAIT(0);
        }
        __syncthreads();

        // GEMM2: y += h @ W2_c
#pragma unroll
        for (int k = 0; k < 8; k++) {
            unsigned a[4], b[16];
            ldsm_x4(smaddr(Hs + (wr + lrow) * 136 + k * 16 + lcol8),
                    a[0], a[1], a[2], a[3]);
#pragma unroll
            for (int j = 0; j < 4; j++)
                ldsm_x4t(smaddr(W2t + (k * 16 + lrow) * 136 + wc + 16 * j + lcol8),
                         b[4*j], b[4*j+1], b[4*j+2], b[4*j+3]);
#pragma unroll
            for (int n = 0; n < 8; n++)
                mma16816(&y[n*4], a[0], a[1], a[2], a[3],
                         b[4*(n>>1) + (n&1)*2], b[4*(n>>1) + (n&1)*2 + 1]);
        }
    }

    __syncthreads();           // reuse smem as float Cs

#pragma unroll
    for (int n = 0; n < 8; n++) {
        const int colb = wc + n * 8 + (lane & 3) * 2;
        const int r0 = wr + (lane >> 2);
        *(float2*)&Cs[r0][colb]   = make_float2(y[n*4+0], y[n*4+1]);
        *(float2*)&Cs[r0+8][colb] = make_float2(y[n*4+2], y[n*4+3]);
    }
    __syncthreads();

    // +b2 +residual(rst float) -> LayerNorm -> out (8 rows per warp)
    {
        const int col = lane * 4;
        const float4 bi = *(const float4*)(b2 + col);
        const float4 g4 = *(const float4*)(lng + col);
        const float4 b4 = *(const float4*)(lnb + col);
#pragma unroll
        for (int rr = 0; rr < 8; rr++) {
            const int r = wid * 8 + rr;
            const int grow = rowBase + r;
            float4 v = *(const float4*)&Cs[r][col];
            const float4 rs = *(const float4*)(g_rst + (size_t)grow * DIM + col);
            float x0 = v.x + bi.x + rs.x;
            float x1 = v.y + bi.y + rs.y;
            float x2 = v.z + bi.z + rs.z;
            float x3 = v.w + bi.w + rs.w;
            float sum = x0 + x1 + x2 + x3;
            float sq = x0 * x0 + x1 * x1 + x2 * x2 + x3 * x3;
#pragma unroll
            for (int o = 16; o; o >>= 1) {
                sum += __shfl_xor_sync(0xffffffffu, sum, o);
                sq  += __shfl_xor_sync(0xffffffffu, sq, o);
            }
            const float mu = sum * (1.f / DIM);
            const float var = sq * (1.f / DIM) - mu * mu;
            const float rstd = rsqrtf(var + LN_EPS);
            float4 o4;
            o4.x = (x0 - mu) * rstd * g4.x + b4.x;
            o4.y = (x1 - mu) * rstd * g4.y + b4.y;
            o4.z = (x2 - mu) * rstd * g4.z + b4.z;
            o4.w = (x3 - mu) * rstd * g4.w + b4.w;
            if (grow < N_NODES)
                *(float4*)(out + (size_t)grow * DIM + col) = o4;
        }
    }
}

// ---------------- dtype conversion (FFN weights only) ------------------------
__global__ void cvt_w12_kernel(const float* __restrict__ W1,
                               const float* __restrict__ W2)
{
    int i = blockIdx.x * blockDim.x + threadIdx.x;
    if (i < 128 * 512) g_w1_h[i] = __float2half(W1[i]);
    else {
        int j = i - 128 * 512;
        if (j < 512 * 128) g_w2_h[j] = __float2half(W2[j]);
    }
}

// ---------------- CSR construction -----------------------------------------
// 16 edges per thread for deep atomic MLP (ATOMG return latency ~318 cyc).
__global__ void hist16_kernel(const int4* __restrict__ dst4, int e4)
{
    int i = (blockIdx.x * blockDim.x + threadIdx.x) * 4;
    if (i + 4 <= e4) {
        int4 d0 = dst4[i], d1 = dst4[i + 1], d2 = dst4[i + 2], d3 = dst4[i + 3];
        atomicAdd(&g_cur[d0.x], 1); atomicAdd(&g_cur[d0.y], 1);
        atomicAdd(&g_cur[d0.z], 1); atomicAdd(&g_cur[d0.w], 1);
        atomicAdd(&g_cur[d1.x], 1); atomicAdd(&g_cur[d1.y], 1);
        atomicAdd(&g_cur[d1.z], 1); atomicAdd(&g_cur[d1.w], 1);
        atomicAdd(&g_cur[d2.x], 1); atomicAdd(&g_cur[d2.y], 1);
        atomicAdd(&g_cur[d2.z], 1); atomicAdd(&g_cur[d2.w], 1);
        atomicAdd(&g_cur[d3.x], 1); atomicAdd(&g_cur[d3.y], 1);
        atomicAdd(&g_cur[d3.z], 1); atomicAdd(&g_cur[d3.w], 1);
    } else {
        for (int j = i; j < e4; j++) {
            int4 d = dst4[j];
            atomicAdd(&g_cur[d.x], 1); atomicAdd(&g_cur[d.y], 1);
            atomicAdd(&g_cur[d.z], 1); atomicAdd(&g_cur[d.w], 1);
        }
    }
}

#define SB 256
#define NSB ((N_NODES + SB - 1) / SB)    // 157 (all co-resident)

__global__ __launch_bounds__(SB)
void scan_lb_kernel(int n)
{
    __shared__ int sh[SB];
    __shared__ int s_excl;
    const int t = threadIdx.x;
    const int b = blockIdx.x;
    const int i = b * SB + t;
    const int v = (i < n) ? g_cur[i] : 0;
    sh[t] = v;
    __syncthreads();
    for (int o = 1; o < SB; o <<= 1) {
        int x = (t >= o) ? sh[t - o] : 0;
        __syncthreads();
        sh[t] += x;
        __syncthreads();
    }
    const int total = sh[SB - 1];

    if (t < 32) {
        if (t == 0) {
            unsigned long long pack = (1ULL << 32) | (unsigned)total;
            atomicExch(&g_state[b], pack);
        }
        __syncwarp();
        int excl = 0;
        int base = b - 1;
        bool done = (b == 0);
        while (!done) {
            const int idx = base - t;
            unsigned long long st;
            unsigned flag;
            if (idx >= 0) {
                do {
                    st = *(volatile unsigned long long*)&g_state[idx];
                    flag = (unsigned)(st >> 32);
                } while (flag == 0);
            } else {
                st = (2ULL << 32);
                flag = 2;
            }
            const unsigned incl_mask = __ballot_sync(0xffffffffu, flag == 2);
            const int first_incl = incl_mask ? (__ffs(incl_mask) - 1) : 32;
            int contrib = (t <= first_incl) ? (int)(unsigned)st : 0;
#pragma unroll
            for (int o = 16; o; o >>= 1)
                contrib += __shfl_xor_sync(0xffffffffu, contrib, o);
            excl += contrib;
            if (first_incl < 32) done = true;
            else { base -= 32; if (base < 0) done = true; }
        }
        if (t == 0) {
            unsigned long long pack = (2ULL << 32) | (unsigned)(excl + total);
            atomicExch(&g_state[b], pack);
            s_excl = excl;
        }
    }
    __syncthreads();

    const int off = s_excl + sh[t] - v;
    if (i < n) {
        g_off[i] = off;
        g_cur[i] = off;
    }
    if (b == NSB - 1 && t == SB - 1) g_off[n] = s_excl + total;
}

__global__ void scatter16_kernel(const int4* __restrict__ src4,
                                 const int4* __restrict__ dst4, int e4)
{
    int i = (blockIdx.x * blockDim.x + threadIdx.x) * 4;
    if (i + 4 <= e4) {
        int4 s0 = src4[i], s1 = src4[i + 1], s2 = src4[i + 2], s3 = src4[i + 3];
        int4 d0 = dst4[i], d1 = dst4[i + 1], d2 = dst4[i + 2], d3 = dst4[i + 3];
        int p0x = atomicAdd(&g_cur[d0.x], 1), p0y = atomicAdd(&g_cur[d0.y], 1);
        int p0z = atomicAdd(&g_cur[d0.z], 1), p0w = atomicAdd(&g_cur[d0.w], 1);
        int p1x = atomicAdd(&g_cur[d1.x], 1), p1y = atomicAdd(&g_cur[d1.y], 1);
        int p1z = atomicAdd(&g_cur[d1.z], 1), p1w = atomicAdd(&g_cur[d1.w], 1);
        int p2x = atomicAdd(&g_cur[d2.x], 1), p2y = atomicAdd(&g_cur[d2.y], 1);
        int p2z = atomicAdd(&g_cur[d2.z], 1), p2w = atomicAdd(&g_cur[d2.w], 1);
        int p3x = atomicAdd(&g_cur[d3.x], 1), p3y = atomicAdd(&g_cur[d3.y], 1);
        int p3z = atomicAdd(&g_cur[d3.z], 1), p3w = atomicAdd(&g_cur[d3.w], 1);
        g_esrc[p0x] = s0.x; g_esrc[p0y] = s0.y; g_esrc[p0z] = s0.z; g_esrc[p0w] = s0.w;
        g_esrc[p1x] = s1.x; g_esrc[p1y] = s1.y; g_esrc[p1z] = s1.z; g_esrc[p1w] = s1.w;
        g_esrc[p2x] = s2.x; g_esrc[p2y] = s2.y; g_esrc[p2z] = s2.z; g_esrc[p2w] = s2.w;
        g_esrc[p3x] = s3.x; g_esrc[p3y] = s3.y; g_esrc[p3z] = s3.z; g_esrc[p3w] = s3.w;
    } else {
        for (int j = i; j < e4; j++) {
            int4 s = src4[j];
            int4 d = dst4[j];
            g_esrc[atomicAdd(&g_cur[d.x], 1)] = s.x;
            g_esrc[atomicAdd(&g_cur[d.y], 1)] = s.y;
            g_esrc[atomicAdd(&g_cur[d.z], 1)] = s.z;
            g_esrc[atomicAdd(&g_cur[d.w], 1)] = s.w;
        }
    }
}

// tail cleanup: restore g_cur/g_state to zero for the next replay
// (runs off the critical path, concurrent with attention/FFN)
__global__ void cleanup_kernel()
{
    int i = blockIdx.x * blockDim.x + threadIdx.x;
    if (i < N_NODES) g_cur[i] = 0;
    if (i < 256) g_state[i] = 0ULL;
}

// ---------------- attention (no-max softmax; scores are O(1) by construction)
__device__ __forceinline__ void kv_unpack(uint4 raw, float4& k4, float4& v4)
{
    float2 a = __half22float2(*(const __half2*)&raw.x);
    float2 b = __half22float2(*(const __half2*)&raw.y);
    float2 c = __half22float2(*(const __half2*)&raw.z);
    float2 d = __half22float2(*(const __half2*)&raw.w);
    k4 = make_float4(a.x, a.y, b.x, b.y);
    v4 = make_float4(c.x, c.y, d.x, d.y);
}

__device__ __forceinline__ float4 ld_half4(const __half* p)
{
    const __half2 h0 = *(const __half2*)(p);
    const __half2 h1 = *(const __half2*)(p + 2);
    const float2 a = __half22float2(h0);
    const float2 b = __half22float2(h1);
    return make_float4(a.x, a.y, b.x, b.y);
}

__device__ __forceinline__ void attn_step(uint4 raw, float4 q4,
                                          float& s, float4& acc)
{
    float4 k4, v4;
    kv_unpack(raw, k4, v4);
    float x = q4.x * k4.x + q4.y * k4.y + q4.z * k4.z + q4.w * k4.w;
    x += __shfl_xor_sync(0xffffffffu, x, 1);
    x += __shfl_xor_sync(0xffffffffu, x, 2);
    const float w = __expf(x * 0.08838834764831845f);   // 1/sqrt(128)
    s += w;
    acc.x += w * v4.x;
    acc.y += w * v4.y;
    acc.z += w * v4.z;
    acc.w += w * v4.w;
}

__global__ __launch_bounds__(256)
void attn_ln1_kernel(const float* __restrict__ feat,
                     const float* __restrict__ ln1g,
                     const float* __restrict__ ln1b)
{
    const int gw = (blockIdx.x * blockDim.x + threadIdx.x) >> 5;
    if (gw >= N_NODES) return;
    const int lane = threadIdx.x & 31;
    const int col = lane * 4;

    const float4 q4 = ld_half4(g_qkv + (size_t)gw * QKV_LD + col);

    float s = 0.f;
    float4 acc = make_float4(0, 0, 0, 0);

    const int beg = g_off[gw], end = g_off[gw + 1];
    int t = beg;
    for (; t + 8 <= end; t += 8) {
        uint4 r[8];
#pragma unroll
        for (int j = 0; j < 8; j++)
            r[j] = *(const uint4*)(g_qkv + (size_t)g_esrc[t + j] * QKV_LD + 128 + lane * 8);
#pragma unroll
        for (int j = 0; j < 8; j++)
            attn_step(r[j], q4, s, acc);
    }
    for (; t < end; t++) {
        const uint4 r = *(const uint4*)(g_qkv + (size_t)g_esrc[t] * QKV_LD + 128 + lane * 8);
        attn_step(r, q4, s, acc);
    }

    const float inv = (s > 0.f) ? (1.f / s) : 0.f;
    const float4 f4 = *(const float4*)(feat + (size_t)gw * DIM + col);
    float x0 = acc.x * inv + f4.x;
    float x1 = acc.y * inv + f4.y;
    float x2 = acc.z * inv + f4.z;
    float x3 = acc.w * inv + f4.w;

    float sum = x0 + x1 + x2 + x3;
    float sq = x0 * x0 + x1 * x1 + x2 * x2 + x3 * x3;
#pragma unroll
    for (int o = 16; o; o >>= 1) {
        sum += __shfl_xor_sync(0xffffffffu, sum, o);
        sq  += __shfl_xor_sync(0xffffffffu, sq, o);
    }
    const float mu = sum * (1.f / DIM);
    const float var = sq * (1.f / DIM) - mu * mu;
    const float rstd = rsqrtf(var + LN_EPS);

    const float4 g4 = *(const float4*)(ln1g + col);
    const float4 b4 = *(const float4*)(ln1b + col);
    float4 o4;
    o4.x = (x0 - mu) * rstd * g4.x + b4.x;
    o4.y = (x1 - mu) * rstd * g4.y + b4.y;
    o4.z = (x2 - mu) * rstd * g4.z + b4.z;
    o4.w = (x3 - mu) * rstd * g4.w + b4.w;
    *(float4*)(g_rst + (size_t)gw * DIM + col) = o4;
}

// ---------------- launch -----------------------------------------------------
extern "C" void kernel_launch(void* const* d_in, const int* in_sizes, int n_in,
                              void* d_out, int out_size)
{
    const float* feat  = (const float*)d_in[0];
    const int*   src   = (const int*)d_in[1];
    const int*   dst   = (const int*)d_in[2];
    const float* Wq    = (const float*)d_in[3];
    const float* Wk    = (const float*)d_in[4];
    const float* Wv    = (const float*)d_in[5];
    const float* ln1g  = (const float*)d_in[6];
    const float* ln1b  = (const float*)d_in[7];
    const float* ln2g  = (const float*)d_in[8];
    const float* ln2b  = (const float*)d_in[9];
    const float* W1    = (const float*)d_in[10];
    const float* b1    = (const float*)d_in[11];
    const float* prelu = (const float*)d_in[12];
    const float* W2    = (const float*)d_in[13];
    const float* b2    = (const float*)d_in[14];
    float* out = (float*)d_out;

    const int E = in_sizes[1];
    const int E4 = E / 4;
    const int NT16 = (E4 + 3) / 4;    // threads for 16-edge kernels

    void* p;
    __half* qkv;
    cudaGetSymbolAddress(&p, g_qkv);
    qkv = (__half*)p;

    static bool init_done = false;
    static cudaStream_t s_side;
    static cudaEvent_t ev_fork, ev_csr, ev_w12, ev_clean;
    if (!init_done) {
        cudaStreamCreateWithFlags(&s_side, cudaStreamNonBlocking);
        cudaEventCreateWithFlags(&ev_fork, cudaEventDisableTiming);
        cudaEventCreateWithFlags(&ev_csr, cudaEventDisableTiming);
        cudaEventCreateWithFlags(&ev_w12, cudaEventDisableTiming);
        cudaEventCreateWithFlags(&ev_clean, cudaEventDisableTiming);
        cudaFuncSetAttribute(mm_qkv_kernel, cudaFuncAttributeMaxDynamicSharedMemorySize, QSM_BYTES);
        cudaFuncSetAttribute(ffn_fused_kernel, cudaFuncAttributeMaxDynamicSharedMemorySize, FSM_TOTAL);
        init_done = true;
    }

    // fork: CSR construction on side stream, concurrent with QKV
    cudaEventRecord(ev_fork, 0);
    cudaStreamWaitEvent(s_side, ev_fork, 0);

    // main: fused QKV projection straight from float inputs
    mm_qkv_kernel<<<dim3(PAD_N / 128, 1, 3), 256, QSM_BYTES>>>(
        feat, Wq, Wk, Wv, qkv);

    // side: CSR by dst (no head memsets; cleanup_kernel re-zeros at the tail)
    hist16_kernel<<<(NT16 + 255) / 256, 256, 0, s_side>>>((const int4*)dst, E4);
    scan_lb_kernel<<<NSB, SB, 0, s_side>>>(N_NODES);
    scatter16_kernel<<<(NT16 + 255) / 256, 256, 0, s_side>>>(
        (const int4*)src, (const int4*)dst, E4);
    cudaEventRecord(ev_csr, s_side);

    // side (after CSR): FFN weight conversion + state cleanup (off crit path)
    cvt_w12_kernel<<<512, 256, 0, s_side>>>(W1, W2);
    cudaEventRecord(ev_w12, s_side);
    cleanup_kernel<<<(N_NODES + 255) / 256, 256, 0, s_side>>>();
    cudaEventRecord(ev_clean, s_side);

    // attention + residual + LN1 (warp per dst node)
    cudaStreamWaitEvent(0, ev_csr, 0);
    attn_ln1_kernel<<<(N_NODES * 32 + 255) / 256, 256>>>(feat, ln1g, ln1b);

    // fused FFN1 + PReLU + FFN2 + residual + LN2 -> out
    cudaStreamWaitEvent(0, ev_w12, 0);
    ffn_fused_kernel<<<PAD_N / FBM, 256, FSM_TOTAL>>>(b1, prelu, b2, ln2g, ln2b, out);

    // join the side stream's tail so graph capture sees all work joined
    cudaStreamWaitEvent(0, ev_clean, 0);
}